// round 7
// baseline (speedup 1.0000x reference)
#include <cuda_runtime.h>
#include <cuda_bf16.h>

// ============================================================================
// ArcNegFace fused kernel for GB300 (compute_103 base target -> mma.sync path)
//   out[b,c] = 64 * ( onehot*a_lb + (1-onehot)*(rw*cos + rw - 1) )
//   cos = normalized feats @ normalized weight^T
//   Split-bf16 (hi+lo) 3-term MMA => fp32-grade cosine accuracy.
//   R7: epilogue staged through smem (reusing A-tile region) for fully
//       coalesced 128B STG -> cut L1TEX store wavefronts ~4x.
// ============================================================================

#define DEVI __device__ __forceinline__

static constexpr int BATCH = 512;
static constexpr int DIM   = 128;
static constexpr int NCLS  = 100000;
static constexpr int TN    = 128;                       // classes per CTA tile
static constexpr int NTILES = (NCLS + TN - 1) / TN;     // 782

// ArcNegFace constants
static constexpr float COSM   = 0.87758256189037271612f;   // cos(0.5)
static constexpr float SINM   = 0.47942553860420300027f;   // sin(0.5)
static constexpr float THRESH = -0.87758256189037271612f;  // cos(pi-0.5)
static constexpr float MMC    = 0.23971276930210150014f;   // sin(pi-0.5)*0.5
static constexpr float EXP2C  = 0.72134752044448170368f;   // 1/(2*ln2)

// smem: 4 operand tiles, 272B pitch (pad-8 bf16 -> conflict-free ldmatrix)
static constexpr int PITCH   = 272;
static constexpr int TILE_B  = 128 * PITCH;             // 34816
static constexpr int SM_BH = 0;
static constexpr int SM_BL = SM_BH + TILE_B;
static constexpr int SM_AH = SM_BL + TILE_B;
static constexpr int SM_AL = SM_AH + TILE_B;
static constexpr int SMEM_BYTES = SM_AL + TILE_B;       // 139264
// output stage overlays A tiles (dead between mainloop end and next A fill)
static constexpr int PITCHW = 136;                      // floats per stage row
// 128 * 136 * 4 = 69632 == 2*TILE_B  (fits exactly over AH+AL)

// ---------------- device scratch (allocation-free rule) ----------------
__device__ unsigned long long g_Ahi[BATCH * DIM / 4];   // 4x bf16 packed
__device__ unsigned long long g_Alo[BATCH * DIM / 4];
__device__ float g_alb[BATCH];
__device__ int   g_lab[BATCH];

// ---------------- helpers ----------------
DEVI unsigned smem_u32(const void* p) {
    unsigned r;
    asm("{ .reg .u64 t; cvta.to.shared.u64 t, %1; cvt.u32.u64 %0, t; }"
        : "=r"(r) : "l"(p));
    return r;
}
DEVI float ex2f(float x) {
    float y;
    asm("ex2.approx.ftz.f32 %0, %1;" : "=f"(y) : "f"(x));
    return y;
}
DEVI void ldm_x4(unsigned& r0, unsigned& r1, unsigned& r2, unsigned& r3,
                 unsigned addr) {
    asm volatile("ldmatrix.sync.aligned.m8n8.x4.shared.b16 {%0,%1,%2,%3}, [%4];"
                 : "=r"(r0), "=r"(r1), "=r"(r2), "=r"(r3) : "r"(addr));
}
DEVI void mma16816(float* d, const unsigned* a, unsigned b0, unsigned b1) {
    asm volatile(
        "mma.sync.aligned.m16n8k16.row.col.f32.bf16.bf16.f32 "
        "{%0,%1,%2,%3}, {%4,%5,%6,%7}, {%8,%9}, {%0,%1,%2,%3};"
        : "+f"(d[0]), "+f"(d[1]), "+f"(d[2]), "+f"(d[3])
        : "r"(a[0]), "r"(a[1]), "r"(a[2]), "r"(a[3]), "r"(b0), "r"(b1));
}
DEVI unsigned long long pack4(__nv_bfloat16 a, __nv_bfloat16 b,
                              __nv_bfloat16 c, __nv_bfloat16 d) {
    return (unsigned long long)__bfloat16_as_ushort(a)
         | ((unsigned long long)__bfloat16_as_ushort(b) << 16)
         | ((unsigned long long)__bfloat16_as_ushort(c) << 32)
         | ((unsigned long long)__bfloat16_as_ushort(d) << 48);
}
DEVI float rsqrt_ref(float s) {
    float r = rsqrtf(s);
    return r * (1.5f - 0.5f * s * r * r);   // Newton step -> ~fp32 exact
}
DEVI float anf(float cv, float a, float a64, bool isl) {
    float t  = cv - a;
    float rw = 1.2f * ex2f(-EXP2C * t * t);
    float v  = 64.0f * fmaf(rw, cv + 1.0f, -1.0f);
    return isl ? a64 : v;
}

// ============================================================================
// Prep: normalize feats -> split bf16 hi/lo globals; a_lb per row.
// ============================================================================
__global__ void prep_kernel(const float* __restrict__ feats,
                            const int* __restrict__ labels,
                            const float* __restrict__ weight) {
    int b = blockIdx.x * (blockDim.x >> 5) + (threadIdx.x >> 5);
    int lane = threadIdx.x & 31;
    if (b >= BATCH) return;

    float4 v = reinterpret_cast<const float4*>(feats)[b * 32 + lane];
    float s = v.x * v.x + v.y * v.y + v.z * v.z + v.w * v.w;
#pragma unroll
    for (int o = 16; o; o >>= 1) s += __shfl_xor_sync(0xffffffffu, s, o);
    float rinv = rsqrt_ref(s);
    float e0 = v.x * rinv, e1 = v.y * rinv, e2 = v.z * rinv, e3 = v.w * rinv;

    __nv_bfloat16 h0 = __float2bfloat16(e0), h1 = __float2bfloat16(e1);
    __nv_bfloat16 h2 = __float2bfloat16(e2), h3 = __float2bfloat16(e3);
    __nv_bfloat16 l0 = __float2bfloat16(e0 - __bfloat162float(h0));
    __nv_bfloat16 l1 = __float2bfloat16(e1 - __bfloat162float(h1));
    __nv_bfloat16 l2 = __float2bfloat16(e2 - __bfloat162float(h2));
    __nv_bfloat16 l3 = __float2bfloat16(e3 - __bfloat162float(h3));
    g_Ahi[b * 32 + lane] = pack4(h0, h1, h2, h3);
    g_Alo[b * 32 + lane] = pack4(l0, l1, l2, l3);

    int lab = labels[b];
    float4 wv = reinterpret_cast<const float4*>(weight)[(size_t)lab * 32 + lane];
    float sw = wv.x * wv.x + wv.y * wv.y + wv.z * wv.z + wv.w * wv.w;
    float dt = e0 * wv.x + e1 * wv.y + e2 * wv.z + e3 * wv.w;
#pragma unroll
    for (int o = 16; o; o >>= 1) sw += __shfl_xor_sync(0xffffffffu, sw, o);
#pragma unroll
    for (int o = 16; o; o >>= 1) dt += __shfl_xor_sync(0xffffffffu, dt, o);

    if (lane == 0) {
        float rw = rsqrt_ref(sw);
        float c = dt * rw;
        c = fminf(1.0f, fmaxf(-1.0f, c));
        float a = (c > THRESH)
                      ? (c * COSM - SINM * sqrtf(fmaxf(0.0f, 1.0f - c * c)))
                      : (c - MMC);
        g_alb[b] = a;
        g_lab[b] = lab;
    }
}

// ============================================================================
// Main: one CTA (512 thr, 16 warps) per 128-class tile.
// Warp grid 4(m) x 4(n): each warp m32 x n32. 4 M-tiles of 128 rows.
// ============================================================================
extern __shared__ char smem[];

__global__ void __launch_bounds__(512, 1)
arcneg_main(const float* __restrict__ weight, float* __restrict__ out) {
    unsigned sb = smem_u32(smem);
    int tid = threadIdx.x;
    int w = tid >> 5;          // 0..15
    int lane = tid & 31;
    int n0 = blockIdx.x * TN;
    int mw = w >> 2;           // 0..3 : m32 block
    int nw = w & 3;            // 0..3 : n32 block

    // ---- Load + normalize + split weight tile (128 classes x 128 dims) ----
#pragma unroll 4
    for (int k = 0; k < 8; k++) {
        int r = k * 16 + w;
        int c = n0 + r;
        float4 v = make_float4(0.f, 0.f, 0.f, 0.f);
        if (c < NCLS) v = reinterpret_cast<const float4*>(weight)[(size_t)c * 32 + lane];
        float s = v.x * v.x + v.y * v.y + v.z * v.z + v.w * v.w;
#pragma unroll
        for (int o = 16; o; o >>= 1) s += __shfl_xor_sync(0xffffffffu, s, o);
        float rinv = 0.0f;
        if (c < NCLS && s > 1e-30f) rinv = rsqrt_ref(s);
        float e0 = v.x * rinv, e1 = v.y * rinv, e2 = v.z * rinv, e3 = v.w * rinv;
        __nv_bfloat16 h0 = __float2bfloat16(e0), h1 = __float2bfloat16(e1);
        __nv_bfloat16 h2 = __float2bfloat16(e2), h3 = __float2bfloat16(e3);
        __nv_bfloat16 l0 = __float2bfloat16(e0 - __bfloat162float(h0));
        __nv_bfloat16 l1 = __float2bfloat16(e1 - __bfloat162float(h1));
        __nv_bfloat16 l2 = __float2bfloat16(e2 - __bfloat162float(h2));
        __nv_bfloat16 l3 = __float2bfloat16(e3 - __bfloat162float(h3));
        unsigned off = r * PITCH + lane * 8;
        *reinterpret_cast<unsigned long long*>(smem + SM_BH + off) = pack4(h0, h1, h2, h3);
        *reinterpret_cast<unsigned long long*>(smem + SM_BL + off) = pack4(l0, l1, l2, l3);
    }
    __syncthreads();

    // ldmatrix per-lane address patterns (within-tile byte offsets)
    const unsigned aL = (unsigned)((mw * 32 + (lane & 15)) * PITCH + ((lane & 16) >> 1) * 2);
    const unsigned bL = (unsigned)((nw * 32 + (lane & 7) + ((lane & 16) >> 1)) * PITCH + (lane & 8) * 2);

    const unsigned tAbase[3] = {SM_AH, SM_AH, SM_AL};
    const unsigned tBbase[3] = {SM_BH, SM_BL, SM_BH};

    int q = lane >> 2, rr = lane & 3;
    float* stage = reinterpret_cast<float*>(smem + SM_AH);   // overlays A tiles
    int nvalid = NCLS - n0;                                  // valid cols this tile

#pragma unroll 1
    for (int mt = 0; mt < 4; mt++) {
        // ---- fill A tile (hi/lo) from L2-resident globals ----
#pragma unroll 4
        for (int j = tid; j < 4096; j += 512) {
            int row = j >> 5, cc = j & 31;
            unsigned long long hv = g_Ahi[(mt * 128 + row) * 32 + cc];
            unsigned long long lv = g_Alo[(mt * 128 + row) * 32 + cc];
            unsigned off = row * PITCH + cc * 8;
            *reinterpret_cast<unsigned long long*>(smem + SM_AH + off) = hv;
            *reinterpret_cast<unsigned long long*>(smem + SM_AL + off) = lv;
        }
        __syncthreads();

        float acc[2][4][4];
#pragma unroll
        for (int i = 0; i < 2; i++)
#pragma unroll
            for (int j = 0; j < 4; j++)
#pragma unroll
                for (int e = 0; e < 4; e++) acc[i][j][e] = 0.0f;

        // ---- 3 split terms x 8 k-steps ----
#pragma unroll
        for (int t = 0; t < 3; t++) {
            unsigned ab = sb + tAbase[t] + aL;
            unsigned bb = sb + tBbase[t] + bL;
#pragma unroll
            for (int k8 = 0; k8 < 8; k8++) {
                unsigned ka = k8 * 32;          // 16 bf16 = 32 bytes
                unsigned af[2][4], bf[2][4];
#pragma unroll
                for (int mi = 0; mi < 2; mi++)
                    ldm_x4(af[mi][0], af[mi][1], af[mi][2], af[mi][3],
                           ab + mi * (16 * PITCH) + ka);
#pragma unroll
                for (int nj = 0; nj < 2; nj++)
                    ldm_x4(bf[nj][0], bf[nj][1], bf[nj][2], bf[nj][3],
                           bb + nj * (16 * PITCH) + ka);
#pragma unroll
                for (int mi = 0; mi < 2; mi++)
#pragma unroll
                    for (int ni = 0; ni < 4; ni++)
                        mma16816(acc[mi][ni], af[mi],
                                 bf[ni >> 1][(ni & 1) * 2],
                                 bf[ni >> 1][(ni & 1) * 2 + 1]);
            }
        }
        __syncthreads();   // all warps done reading A -> reuse as stage

        // ---- epilogue into smem stage (STS.64, pitch 136 words) ----
#pragma unroll
        for (int mi = 0; mi < 2; mi++) {
            int lr0 = mw * 32 + mi * 16 + q;         // local row in stage
            int lr1 = lr0 + 8;
            int r0 = mt * 128 + lr0;
            int r1 = r0 + 8;
            float av0 = g_alb[r0], av1 = g_alb[r1];
            int   lb0 = g_lab[r0] - n0, lb1 = g_lab[r1] - n0;   // local label col
            float a64_0 = 64.0f * av0, a64_1 = 64.0f * av1;
#pragma unroll
            for (int ni = 0; ni < 4; ni++) {
                int c = nw * 32 + ni * 8 + rr * 2;   // local col 0..127
                float2 v0, v1;
                v0.x = anf(acc[mi][ni][0], av0, a64_0, c == lb0);
                v0.y = anf(acc[mi][ni][1], av0, a64_0, c + 1 == lb0);
                v1.x = anf(acc[mi][ni][2], av1, a64_1, c == lb1);
                v1.y = anf(acc[mi][ni][3], av1, a64_1, c + 1 == lb1);
                *reinterpret_cast<float2*>(&stage[lr0 * PITCHW + c]) = v0;
                *reinterpret_cast<float2*>(&stage[lr1 * PITCHW + c]) = v1;
            }
        }
        __syncthreads();

        // ---- coalesced 512B row stores: warp w -> rows w, w+16, ... ----
        bool valid = lane * 4 < nvalid;              // float4 granularity (nvalid%4==0)
#pragma unroll
        for (int r = w; r < 128; r += 16) {
            if (valid) {
                float4 vv = *reinterpret_cast<float4*>(&stage[r * PITCHW + lane * 4]);
                __stcs(reinterpret_cast<float4*>(out + (size_t)(mt * 128 + r) * NCLS
                                                 + n0 + lane * 4), vv);
            }
        }
        __syncthreads();   // stage (A region) safe to refill next iteration
    }
}

// ============================================================================
extern "C" void kernel_launch(void* const* d_in, const int* in_sizes, int n_in,
                              void* d_out, int out_size) {
    const float* feats = (const float*)d_in[0];
    const int*   labels = (const int*)d_in[1];
    const float* weight = (const float*)d_in[2];
    for (int i = 0; i < n_in; i++) {
        if (in_sizes[i] == BATCH * DIM) feats = (const float*)d_in[i];
        else if (in_sizes[i] == BATCH) labels = (const int*)d_in[i];
        else if (in_sizes[i] == NCLS * DIM) weight = (const float*)d_in[i];
    }
    float* out = (float*)d_out;

    cudaFuncSetAttribute(arcneg_main, cudaFuncAttributeMaxDynamicSharedMemorySize,
                         SMEM_BYTES);

    prep_kernel<<<128, 128>>>(feats, labels, weight);
    arcneg_main<<<NTILES, 512, SMEM_BYTES>>>(weight, out);
}

// round 8
// speedup vs baseline: 1.0668x; 1.0668x over previous
#include <cuda_runtime.h>
#include <cuda_bf16.h>

// ============================================================================
// ArcNegFace fused kernel for GB300 (compute_103 base target -> mma.sync path)
//   out[b,c] = 64 * ( onehot*a_lb + (1-onehot)*(rw*cos + rw - 1) )
//   cos = normalized feats @ normalized weight^T
//   Split-bf16 (hi+lo) 3-term MMA => fp32-grade cosine accuracy.
//   R8: TN=64, 256-thr CTAs, smem 102KB -> 2 CTAs/SM co-resident so one
//       CTA's mainloop overlaps the other's fill/epilogue phases.
// ============================================================================

#define DEVI __device__ __forceinline__

static constexpr int BATCH = 512;
static constexpr int DIM   = 128;
static constexpr int NCLS  = 100000;
static constexpr int TN    = 64;                        // classes per CTA tile
static constexpr int NTILES = (NCLS + TN - 1) / TN;     // 1563

// ArcNegFace constants
static constexpr float COSM   = 0.87758256189037271612f;   // cos(0.5)
static constexpr float SINM   = 0.47942553860420300027f;   // sin(0.5)
static constexpr float THRESH = -0.87758256189037271612f;  // cos(pi-0.5)
static constexpr float MMC    = 0.23971276930210150014f;   // sin(pi-0.5)*0.5
static constexpr float EXP2C  = 0.72134752044448170368f;   // 1/(2*ln2)

// smem: 272B pitch rows (pad-8 bf16 -> conflict-free ldmatrix)
static constexpr int PITCH    = 272;
static constexpr int B_TILE_B = TN * PITCH;             // 17408
static constexpr int A_TILE_B = 128 * PITCH;            // 34816
static constexpr int SM_BH = 0;
static constexpr int SM_BL = SM_BH + B_TILE_B;
static constexpr int SM_AH = SM_BL + B_TILE_B;
static constexpr int SM_AL = SM_AH + A_TILE_B;
static constexpr int SMEM_BYTES = SM_AL + A_TILE_B;     // 104448 (2/SM)

// ---------------- device scratch (allocation-free rule) ----------------
__device__ unsigned long long g_Ahi[BATCH * DIM / 4];   // 4x bf16 packed
__device__ unsigned long long g_Alo[BATCH * DIM / 4];
__device__ float g_alb[BATCH];
__device__ int   g_lab[BATCH];

// ---------------- helpers ----------------
DEVI unsigned smem_u32(const void* p) {
    unsigned r;
    asm("{ .reg .u64 t; cvta.to.shared.u64 t, %1; cvt.u32.u64 %0, t; }"
        : "=r"(r) : "l"(p));
    return r;
}
DEVI float ex2f(float x) {
    float y;
    asm("ex2.approx.ftz.f32 %0, %1;" : "=f"(y) : "f"(x));
    return y;
}
DEVI void ldm_x4(unsigned& r0, unsigned& r1, unsigned& r2, unsigned& r3,
                 unsigned addr) {
    asm volatile("ldmatrix.sync.aligned.m8n8.x4.shared.b16 {%0,%1,%2,%3}, [%4];"
                 : "=r"(r0), "=r"(r1), "=r"(r2), "=r"(r3) : "r"(addr));
}
DEVI void mma16816(float* d, const unsigned* a, unsigned b0, unsigned b1) {
    asm volatile(
        "mma.sync.aligned.m16n8k16.row.col.f32.bf16.bf16.f32 "
        "{%0,%1,%2,%3}, {%4,%5,%6,%7}, {%8,%9}, {%0,%1,%2,%3};"
        : "+f"(d[0]), "+f"(d[1]), "+f"(d[2]), "+f"(d[3])
        : "r"(a[0]), "r"(a[1]), "r"(a[2]), "r"(a[3]), "r"(b0), "r"(b1));
}
DEVI unsigned long long pack4(__nv_bfloat16 a, __nv_bfloat16 b,
                              __nv_bfloat16 c, __nv_bfloat16 d) {
    return (unsigned long long)__bfloat16_as_ushort(a)
         | ((unsigned long long)__bfloat16_as_ushort(b) << 16)
         | ((unsigned long long)__bfloat16_as_ushort(c) << 32)
         | ((unsigned long long)__bfloat16_as_ushort(d) << 48);
}
DEVI float rsqrt_ref(float s) {
    float r = rsqrtf(s);
    return r * (1.5f - 0.5f * s * r * r);   // Newton step -> ~fp32 exact
}
DEVI float anf(float cv, float a, float a64, bool isl) {
    float t  = cv - a;
    float rw = 1.2f * ex2f(-EXP2C * t * t);
    float v  = 64.0f * fmaf(rw, cv + 1.0f, -1.0f);
    return isl ? a64 : v;
}

// ============================================================================
// Prep: normalize feats -> split bf16 hi/lo globals; a_lb per row.
// ============================================================================
__global__ void prep_kernel(const float* __restrict__ feats,
                            const int* __restrict__ labels,
                            const float* __restrict__ weight) {
    int b = blockIdx.x * (blockDim.x >> 5) + (threadIdx.x >> 5);
    int lane = threadIdx.x & 31;
    if (b >= BATCH) return;

    float4 v = reinterpret_cast<const float4*>(feats)[b * 32 + lane];
    float s = v.x * v.x + v.y * v.y + v.z * v.z + v.w * v.w;
#pragma unroll
    for (int o = 16; o; o >>= 1) s += __shfl_xor_sync(0xffffffffu, s, o);
    float rinv = rsqrt_ref(s);
    float e0 = v.x * rinv, e1 = v.y * rinv, e2 = v.z * rinv, e3 = v.w * rinv;

    __nv_bfloat16 h0 = __float2bfloat16(e0), h1 = __float2bfloat16(e1);
    __nv_bfloat16 h2 = __float2bfloat16(e2), h3 = __float2bfloat16(e3);
    __nv_bfloat16 l0 = __float2bfloat16(e0 - __bfloat162float(h0));
    __nv_bfloat16 l1 = __float2bfloat16(e1 - __bfloat162float(h1));
    __nv_bfloat16 l2 = __float2bfloat16(e2 - __bfloat162float(h2));
    __nv_bfloat16 l3 = __float2bfloat16(e3 - __bfloat162float(h3));
    g_Ahi[b * 32 + lane] = pack4(h0, h1, h2, h3);
    g_Alo[b * 32 + lane] = pack4(l0, l1, l2, l3);

    int lab = labels[b];
    float4 wv = reinterpret_cast<const float4*>(weight)[(size_t)lab * 32 + lane];
    float sw = wv.x * wv.x + wv.y * wv.y + wv.z * wv.z + wv.w * wv.w;
    float dt = e0 * wv.x + e1 * wv.y + e2 * wv.z + e3 * wv.w;
#pragma unroll
    for (int o = 16; o; o >>= 1) sw += __shfl_xor_sync(0xffffffffu, sw, o);
#pragma unroll
    for (int o = 16; o; o >>= 1) dt += __shfl_xor_sync(0xffffffffu, dt, o);

    if (lane == 0) {
        float rw = rsqrt_ref(sw);
        float c = dt * rw;
        c = fminf(1.0f, fmaxf(-1.0f, c));
        float a = (c > THRESH)
                      ? (c * COSM - SINM * sqrtf(fmaxf(0.0f, 1.0f - c * c)))
                      : (c - MMC);
        g_alb[b] = a;
        g_lab[b] = lab;
    }
}

// ============================================================================
// Main: one CTA (256 thr, 8 warps) per 64-class tile; 2 CTAs/SM.
// Warp grid 4(m) x 2(n): each warp m32 x n32. 4 M-tiles of 128 rows.
// ============================================================================
extern __shared__ char smem[];

__global__ void __launch_bounds__(256, 2)
arcneg_main(const float* __restrict__ weight, float* __restrict__ out) {
    unsigned sb = smem_u32(smem);
    int tid = threadIdx.x;
    int w = tid >> 5;          // 0..7
    int lane = tid & 31;
    int n0 = blockIdx.x * TN;
    int mw = w >> 1;           // 0..3 : m32 block
    int nw = w & 1;            // 0..1 : n32 block

    // ---- Load + normalize + split weight tile (64 classes x 128 dims) ----
    // Warp handles rows r = k*8 + w; 32 lanes = one full row (32 float4).
#pragma unroll 4
    for (int k = 0; k < 8; k++) {
        int r = k * 8 + w;
        int c = n0 + r;
        float4 v = make_float4(0.f, 0.f, 0.f, 0.f);
        if (c < NCLS) v = reinterpret_cast<const float4*>(weight)[(size_t)c * 32 + lane];
        float s = v.x * v.x + v.y * v.y + v.z * v.z + v.w * v.w;
#pragma unroll
        for (int o = 16; o; o >>= 1) s += __shfl_xor_sync(0xffffffffu, s, o);
        float rinv = 0.0f;
        if (c < NCLS && s > 1e-30f) rinv = rsqrt_ref(s);
        float e0 = v.x * rinv, e1 = v.y * rinv, e2 = v.z * rinv, e3 = v.w * rinv;
        __nv_bfloat16 h0 = __float2bfloat16(e0), h1 = __float2bfloat16(e1);
        __nv_bfloat16 h2 = __float2bfloat16(e2), h3 = __float2bfloat16(e3);
        __nv_bfloat16 l0 = __float2bfloat16(e0 - __bfloat162float(h0));
        __nv_bfloat16 l1 = __float2bfloat16(e1 - __bfloat162float(h1));
        __nv_bfloat16 l2 = __float2bfloat16(e2 - __bfloat162float(h2));
        __nv_bfloat16 l3 = __float2bfloat16(e3 - __bfloat162float(h3));
        unsigned off = r * PITCH + lane * 8;
        *reinterpret_cast<unsigned long long*>(smem + SM_BH + off) = pack4(h0, h1, h2, h3);
        *reinterpret_cast<unsigned long long*>(smem + SM_BL + off) = pack4(l0, l1, l2, l3);
    }
    __syncthreads();

    // ldmatrix per-lane address patterns (within-tile byte offsets)
    const unsigned aL = (unsigned)((mw * 32 + (lane & 15)) * PITCH + ((lane & 16) >> 1) * 2);
    const unsigned bL = (unsigned)((nw * 32 + (lane & 7) + ((lane & 16) >> 1)) * PITCH + (lane & 8) * 2);

    const unsigned tAbase[3] = {SM_AH, SM_AH, SM_AL};
    const unsigned tBbase[3] = {SM_BH, SM_BL, SM_BH};

    int q = lane >> 2, rr = lane & 3;

#pragma unroll 1
    for (int mt = 0; mt < 4; mt++) {
        // ---- fill A tile (hi/lo) from L2-resident globals ----
#pragma unroll 4
        for (int j = tid; j < 4096; j += 256) {
            int row = j >> 5, cc = j & 31;
            unsigned long long hv = g_Ahi[(mt * 128 + row) * 32 + cc];
            unsigned long long lv = g_Alo[(mt * 128 + row) * 32 + cc];
            unsigned off = row * PITCH + cc * 8;
            *reinterpret_cast<unsigned long long*>(smem + SM_AH + off) = hv;
            *reinterpret_cast<unsigned long long*>(smem + SM_AL + off) = lv;
        }
        __syncthreads();

        float acc[2][4][4];
#pragma unroll
        for (int i = 0; i < 2; i++)
#pragma unroll
            for (int j = 0; j < 4; j++)
#pragma unroll
                for (int e = 0; e < 4; e++) acc[i][j][e] = 0.0f;

        // ---- 3 split terms x 8 k-steps ----
#pragma unroll
        for (int t = 0; t < 3; t++) {
            unsigned ab = sb + tAbase[t] + aL;
            unsigned bb = sb + tBbase[t] + bL;
#pragma unroll
            for (int k8 = 0; k8 < 8; k8++) {
                unsigned ka = k8 * 32;          // 16 bf16 = 32 bytes
                unsigned af[2][4], bf[2][4];
#pragma unroll
                for (int mi = 0; mi < 2; mi++)
                    ldm_x4(af[mi][0], af[mi][1], af[mi][2], af[mi][3],
                           ab + mi * (16 * PITCH) + ka);
#pragma unroll
                for (int nj = 0; nj < 2; nj++)
                    ldm_x4(bf[nj][0], bf[nj][1], bf[nj][2], bf[nj][3],
                           bb + nj * (16 * PITCH) + ka);
#pragma unroll
                for (int mi = 0; mi < 2; mi++)
#pragma unroll
                    for (int ni = 0; ni < 4; ni++)
                        mma16816(acc[mi][ni], af[mi],
                                 bf[ni >> 1][(ni & 1) * 2],
                                 bf[ni >> 1][(ni & 1) * 2 + 1]);
            }
        }

        // ---- fused epilogue, direct streaming v2 stores ----
#pragma unroll
        for (int mi = 0; mi < 2; mi++) {
            int r0 = mt * 128 + mw * 32 + mi * 16 + q;
            int r1 = r0 + 8;
            float av0 = g_alb[r0], av1 = g_alb[r1];
            int   lb0 = g_lab[r0], lb1 = g_lab[r1];
            float a64_0 = 64.0f * av0, a64_1 = 64.0f * av1;
#pragma unroll
            for (int ni = 0; ni < 4; ni++) {
                int c = n0 + nw * 32 + ni * 8 + rr * 2;
                if (c < NCLS) {
                    float2 v0, v1;
                    v0.x = anf(acc[mi][ni][0], av0, a64_0, c == lb0);
                    v0.y = anf(acc[mi][ni][1], av0, a64_0, c + 1 == lb0);
                    v1.x = anf(acc[mi][ni][2], av1, a64_1, c == lb1);
                    v1.y = anf(acc[mi][ni][3], av1, a64_1, c + 1 == lb1);
                    __stcs(reinterpret_cast<float2*>(out + (size_t)r0 * NCLS + c), v0);
                    __stcs(reinterpret_cast<float2*>(out + (size_t)r1 * NCLS + c), v1);
                }
            }
        }
        __syncthreads();   // A smem safe to overwrite next iteration
    }
}

// ============================================================================
extern "C" void kernel_launch(void* const* d_in, const int* in_sizes, int n_in,
                              void* d_out, int out_size) {
    const float* feats = (const float*)d_in[0];
    const int*   labels = (const int*)d_in[1];
    const float* weight = (const float*)d_in[2];
    for (int i = 0; i < n_in; i++) {
        if (in_sizes[i] == BATCH * DIM) feats = (const float*)d_in[i];
        else if (in_sizes[i] == BATCH) labels = (const int*)d_in[i];
        else if (in_sizes[i] == NCLS * DIM) weight = (const float*)d_in[i];
    }
    float* out = (float*)d_out;

    cudaFuncSetAttribute(arcneg_main, cudaFuncAttributeMaxDynamicSharedMemorySize,
                         SMEM_BYTES);

    prep_kernel<<<128, 128>>>(feats, labels, weight);
    arcneg_main<<<NTILES, 256, SMEM_BYTES>>>(weight, out);
}

// round 9
// speedup vs baseline: 1.3870x; 1.3002x over previous
#include <cuda_runtime.h>
#include <cuda_bf16.h>

// ============================================================================
// ArcNegFace fused kernel for GB300 (compute_103 base target -> mma.sync path)
//   out[b,c] = 64 * ( onehot*a_lb + (1-onehot)*(rw*cos + rw - 1) )
//   cos = normalized feats @ normalized weight^T
//   Split-bf16 (hi+lo) 3-term MMA => fp32-grade cosine accuracy.
//   R9: fragment loads hoisted across the 3 split terms: per k-step
//       8 LDSM -> 24 HMMA (was 12 LDSM interleaved 3x8) to triple the
//       tensor-pipe duty cycle per load burst.
// ============================================================================

#define DEVI __device__ __forceinline__

static constexpr int BATCH = 512;
static constexpr int DIM   = 128;
static constexpr int NCLS  = 100000;
static constexpr int TN    = 128;                       // classes per CTA tile
static constexpr int NTILES = (NCLS + TN - 1) / TN;     // 782

// ArcNegFace constants
static constexpr float COSM   = 0.87758256189037271612f;   // cos(0.5)
static constexpr float SINM   = 0.47942553860420300027f;   // sin(0.5)
static constexpr float THRESH = -0.87758256189037271612f;  // cos(pi-0.5)
static constexpr float MMC    = 0.23971276930210150014f;   // sin(pi-0.5)*0.5
static constexpr float EXP2C  = 0.72134752044448170368f;   // 1/(2*ln2)

// smem: 4 operand tiles, 272B pitch (pad-8 bf16 -> conflict-free ldmatrix)
static constexpr int PITCH   = 272;
static constexpr int TILE_B  = 128 * PITCH;             // 34816
static constexpr int SM_BH = 0;
static constexpr int SM_BL = SM_BH + TILE_B;
static constexpr int SM_AH = SM_BL + TILE_B;
static constexpr int SM_AL = SM_AH + TILE_B;
static constexpr int SMEM_BYTES = SM_AL + TILE_B;       // 139264

// ---------------- device scratch (allocation-free rule) ----------------
__device__ unsigned long long g_Ahi[BATCH * DIM / 4];   // 4x bf16 packed
__device__ unsigned long long g_Alo[BATCH * DIM / 4];
__device__ float g_alb[BATCH];
__device__ int   g_lab[BATCH];

// ---------------- helpers ----------------
DEVI unsigned smem_u32(const void* p) {
    unsigned r;
    asm("{ .reg .u64 t; cvta.to.shared.u64 t, %1; cvt.u32.u64 %0, t; }"
        : "=r"(r) : "l"(p));
    return r;
}
DEVI float ex2f(float x) {
    float y;
    asm("ex2.approx.ftz.f32 %0, %1;" : "=f"(y) : "f"(x));
    return y;
}
DEVI void ldm_x4(unsigned& r0, unsigned& r1, unsigned& r2, unsigned& r3,
                 unsigned addr) {
    asm volatile("ldmatrix.sync.aligned.m8n8.x4.shared.b16 {%0,%1,%2,%3}, [%4];"
                 : "=r"(r0), "=r"(r1), "=r"(r2), "=r"(r3) : "r"(addr));
}
DEVI void mma16816(float* d, const unsigned* a, unsigned b0, unsigned b1) {
    asm volatile(
        "mma.sync.aligned.m16n8k16.row.col.f32.bf16.bf16.f32 "
        "{%0,%1,%2,%3}, {%4,%5,%6,%7}, {%8,%9}, {%0,%1,%2,%3};"
        : "+f"(d[0]), "+f"(d[1]), "+f"(d[2]), "+f"(d[3])
        : "r"(a[0]), "r"(a[1]), "r"(a[2]), "r"(a[3]), "r"(b0), "r"(b1));
}
DEVI unsigned long long pack4(__nv_bfloat16 a, __nv_bfloat16 b,
                              __nv_bfloat16 c, __nv_bfloat16 d) {
    return (unsigned long long)__bfloat16_as_ushort(a)
         | ((unsigned long long)__bfloat16_as_ushort(b) << 16)
         | ((unsigned long long)__bfloat16_as_ushort(c) << 32)
         | ((unsigned long long)__bfloat16_as_ushort(d) << 48);
}
DEVI float rsqrt_ref(float s) {
    float r = rsqrtf(s);
    return r * (1.5f - 0.5f * s * r * r);   // Newton step -> ~fp32 exact
}
DEVI float anf(float cv, float a, float a64, bool isl) {
    float t  = cv - a;
    float rw = 1.2f * ex2f(-EXP2C * t * t);
    float v  = 64.0f * fmaf(rw, cv + 1.0f, -1.0f);
    return isl ? a64 : v;
}

// ============================================================================
// Prep: normalize feats -> split bf16 hi/lo globals; a_lb per row.
// ============================================================================
__global__ void prep_kernel(const float* __restrict__ feats,
                            const int* __restrict__ labels,
                            const float* __restrict__ weight) {
    int b = blockIdx.x * (blockDim.x >> 5) + (threadIdx.x >> 5);
    int lane = threadIdx.x & 31;
    if (b >= BATCH) return;

    float4 v = reinterpret_cast<const float4*>(feats)[b * 32 + lane];
    float s = v.x * v.x + v.y * v.y + v.z * v.z + v.w * v.w;
#pragma unroll
    for (int o = 16; o; o >>= 1) s += __shfl_xor_sync(0xffffffffu, s, o);
    float rinv = rsqrt_ref(s);
    float e0 = v.x * rinv, e1 = v.y * rinv, e2 = v.z * rinv, e3 = v.w * rinv;

    __nv_bfloat16 h0 = __float2bfloat16(e0), h1 = __float2bfloat16(e1);
    __nv_bfloat16 h2 = __float2bfloat16(e2), h3 = __float2bfloat16(e3);
    __nv_bfloat16 l0 = __float2bfloat16(e0 - __bfloat162float(h0));
    __nv_bfloat16 l1 = __float2bfloat16(e1 - __bfloat162float(h1));
    __nv_bfloat16 l2 = __float2bfloat16(e2 - __bfloat162float(h2));
    __nv_bfloat16 l3 = __float2bfloat16(e3 - __bfloat162float(h3));
    g_Ahi[b * 32 + lane] = pack4(h0, h1, h2, h3);
    g_Alo[b * 32 + lane] = pack4(l0, l1, l2, l3);

    int lab = labels[b];
    float4 wv = reinterpret_cast<const float4*>(weight)[(size_t)lab * 32 + lane];
    float sw = wv.x * wv.x + wv.y * wv.y + wv.z * wv.z + wv.w * wv.w;
    float dt = e0 * wv.x + e1 * wv.y + e2 * wv.z + e3 * wv.w;
#pragma unroll
    for (int o = 16; o; o >>= 1) sw += __shfl_xor_sync(0xffffffffu, sw, o);
#pragma unroll
    for (int o = 16; o; o >>= 1) dt += __shfl_xor_sync(0xffffffffu, dt, o);

    if (lane == 0) {
        float rw = rsqrt_ref(sw);
        float c = dt * rw;
        c = fminf(1.0f, fmaxf(-1.0f, c));
        float a = (c > THRESH)
                      ? (c * COSM - SINM * sqrtf(fmaxf(0.0f, 1.0f - c * c)))
                      : (c - MMC);
        g_alb[b] = a;
        g_lab[b] = lab;
    }
}

// ============================================================================
// Main: one CTA (512 thr, 16 warps) per 128-class tile.
// Warp grid 4(m) x 4(n): each warp m32 x n32. 4 M-tiles of 128 rows.
// ============================================================================
extern __shared__ char smem[];

__global__ void __launch_bounds__(512, 1)
arcneg_main(const float* __restrict__ weight, float* __restrict__ out) {
    unsigned sb = smem_u32(smem);
    int tid = threadIdx.x;
    int w = tid >> 5;          // 0..15
    int lane = tid & 31;
    int n0 = blockIdx.x * TN;
    int mw = w >> 2;           // 0..3 : m32 block
    int nw = w & 3;            // 0..3 : n32 block

    // ---- Load + normalize + split weight tile (128 classes x 128 dims) ----
#pragma unroll 4
    for (int k = 0; k < 8; k++) {
        int r = k * 16 + w;
        int c = n0 + r;
        float4 v = make_float4(0.f, 0.f, 0.f, 0.f);
        if (c < NCLS) v = reinterpret_cast<const float4*>(weight)[(size_t)c * 32 + lane];
        float s = v.x * v.x + v.y * v.y + v.z * v.z + v.w * v.w;
#pragma unroll
        for (int o = 16; o; o >>= 1) s += __shfl_xor_sync(0xffffffffu, s, o);
        float rinv = 0.0f;
        if (c < NCLS && s > 1e-30f) rinv = rsqrt_ref(s);
        float e0 = v.x * rinv, e1 = v.y * rinv, e2 = v.z * rinv, e3 = v.w * rinv;
        __nv_bfloat16 h0 = __float2bfloat16(e0), h1 = __float2bfloat16(e1);
        __nv_bfloat16 h2 = __float2bfloat16(e2), h3 = __float2bfloat16(e3);
        __nv_bfloat16 l0 = __float2bfloat16(e0 - __bfloat162float(h0));
        __nv_bfloat16 l1 = __float2bfloat16(e1 - __bfloat162float(h1));
        __nv_bfloat16 l2 = __float2bfloat16(e2 - __bfloat162float(h2));
        __nv_bfloat16 l3 = __float2bfloat16(e3 - __bfloat162float(h3));
        unsigned off = r * PITCH + lane * 8;
        *reinterpret_cast<unsigned long long*>(smem + SM_BH + off) = pack4(h0, h1, h2, h3);
        *reinterpret_cast<unsigned long long*>(smem + SM_BL + off) = pack4(l0, l1, l2, l3);
    }
    __syncthreads();

    // ldmatrix per-lane address patterns (within-tile byte offsets)
    const unsigned aL = (unsigned)((mw * 32 + (lane & 15)) * PITCH + ((lane & 16) >> 1) * 2);
    const unsigned bL = (unsigned)((nw * 32 + (lane & 7) + ((lane & 16) >> 1)) * PITCH + (lane & 8) * 2);

    int q = lane >> 2, rr = lane & 3;

#pragma unroll 1
    for (int mt = 0; mt < 4; mt++) {
        // ---- fill A tile (hi/lo) from L2-resident globals ----
#pragma unroll 4
        for (int j = tid; j < 4096; j += 512) {
            int row = j >> 5, cc = j & 31;
            unsigned long long hv = g_Ahi[(mt * 128 + row) * 32 + cc];
            unsigned long long lv = g_Alo[(mt * 128 + row) * 32 + cc];
            unsigned off = row * PITCH + cc * 8;
            *reinterpret_cast<unsigned long long*>(smem + SM_AH + off) = hv;
            *reinterpret_cast<unsigned long long*>(smem + SM_AL + off) = lv;
        }
        __syncthreads();

        float acc[2][4][4];
#pragma unroll
        for (int i = 0; i < 2; i++)
#pragma unroll
            for (int j = 0; j < 4; j++)
#pragma unroll
                for (int e = 0; e < 4; e++) acc[i][j][e] = 0.0f;

        // ---- mainloop: per k-step load all 8 fragments once, 24 HMMA ----
#pragma unroll
        for (int k8 = 0; k8 < 8; k8++) {
            unsigned ka = k8 * 32;              // 16 bf16 = 32 bytes
            unsigned ah[2][4], al[2][4], bh[2][4], bl[2][4];
            // hi fragments first: the hi*hi MMAs can start while lo loads land
#pragma unroll
            for (int mi = 0; mi < 2; mi++)
                ldm_x4(ah[mi][0], ah[mi][1], ah[mi][2], ah[mi][3],
                       sb + SM_AH + aL + mi * (16 * PITCH) + ka);
#pragma unroll
            for (int nj = 0; nj < 2; nj++)
                ldm_x4(bh[nj][0], bh[nj][1], bh[nj][2], bh[nj][3],
                       sb + SM_BH + bL + nj * (16 * PITCH) + ka);
#pragma unroll
            for (int mi = 0; mi < 2; mi++)
                ldm_x4(al[mi][0], al[mi][1], al[mi][2], al[mi][3],
                       sb + SM_AL + aL + mi * (16 * PITCH) + ka);
#pragma unroll
            for (int nj = 0; nj < 2; nj++)
                ldm_x4(bl[nj][0], bl[nj][1], bl[nj][2], bl[nj][3],
                       sb + SM_BL + bL + nj * (16 * PITCH) + ka);

            // hi*hi
#pragma unroll
            for (int mi = 0; mi < 2; mi++)
#pragma unroll
                for (int ni = 0; ni < 4; ni++)
                    mma16816(acc[mi][ni], ah[mi],
                             bh[ni >> 1][(ni & 1) * 2],
                             bh[ni >> 1][(ni & 1) * 2 + 1]);
            // hi*lo
#pragma unroll
            for (int mi = 0; mi < 2; mi++)
#pragma unroll
                for (int ni = 0; ni < 4; ni++)
                    mma16816(acc[mi][ni], ah[mi],
                             bl[ni >> 1][(ni & 1) * 2],
                             bl[ni >> 1][(ni & 1) * 2 + 1]);
            // lo*hi
#pragma unroll
            for (int mi = 0; mi < 2; mi++)
#pragma unroll
                for (int ni = 0; ni < 4; ni++)
                    mma16816(acc[mi][ni], al[mi],
                             bh[ni >> 1][(ni & 1) * 2],
                             bh[ni >> 1][(ni & 1) * 2 + 1]);
        }

        // ---- fused epilogue, direct streaming v2 stores ----
#pragma unroll
        for (int mi = 0; mi < 2; mi++) {
            int r0 = mt * 128 + mw * 32 + mi * 16 + q;
            int r1 = r0 + 8;
            float av0 = g_alb[r0], av1 = g_alb[r1];
            int   lb0 = g_lab[r0], lb1 = g_lab[r1];
            float a64_0 = 64.0f * av0, a64_1 = 64.0f * av1;
#pragma unroll
            for (int ni = 0; ni < 4; ni++) {
                int c = n0 + nw * 32 + ni * 8 + rr * 2;
                if (c < NCLS) {
                    float2 v0, v1;
                    v0.x = anf(acc[mi][ni][0], av0, a64_0, c == lb0);
                    v0.y = anf(acc[mi][ni][1], av0, a64_0, c + 1 == lb0);
                    v1.x = anf(acc[mi][ni][2], av1, a64_1, c == lb1);
                    v1.y = anf(acc[mi][ni][3], av1, a64_1, c + 1 == lb1);
                    __stcs(reinterpret_cast<float2*>(out + (size_t)r0 * NCLS + c), v0);
                    __stcs(reinterpret_cast<float2*>(out + (size_t)r1 * NCLS + c), v1);
                }
            }
        }
        __syncthreads();   // A smem safe to overwrite next iteration
    }
}

// ============================================================================
extern "C" void kernel_launch(void* const* d_in, const int* in_sizes, int n_in,
                              void* d_out, int out_size) {
    const float* feats = (const float*)d_in[0];
    const int*   labels = (const int*)d_in[1];
    const float* weight = (const float*)d_in[2];
    for (int i = 0; i < n_in; i++) {
        if (in_sizes[i] == BATCH * DIM) feats = (const float*)d_in[i];
        else if (in_sizes[i] == BATCH) labels = (const int*)d_in[i];
        else if (in_sizes[i] == NCLS * DIM) weight = (const float*)d_in[i];
    }
    float* out = (float*)d_out;

    cudaFuncSetAttribute(arcneg_main, cudaFuncAttributeMaxDynamicSharedMemorySize,
                         SMEM_BYTES);

    prep_kernel<<<128, 128>>>(feats, labels, weight);
    arcneg_main<<<NTILES, 512, SMEM_BYTES>>>(weight, out);
}

// round 10
// speedup vs baseline: 1.5298x; 1.1030x over previous
#include <cuda_runtime.h>
#include <cuda_bf16.h>

// ============================================================================
// ArcNegFace fused kernel for GB300 (compute_103 base target -> mma.sync path)
//   out[b,c] = 64 * ( onehot*a_lb + (1-onehot)*(rw*cos + rw - 1) )
//   cos = normalized feats @ normalized weight^T
//   Split-bf16 (hi+lo) 3-term MMA => fp32-grade cosine accuracy.
//   R10: A tiles double-buffered + filled via cp.async (overlaps mainloop);
//        one __syncthreads per M-tile; fill for mt0 overlaps B prologue.
// ============================================================================

#define DEVI __device__ __forceinline__

static constexpr int BATCH = 512;
static constexpr int DIM   = 128;
static constexpr int NCLS  = 100000;
static constexpr int TN    = 128;                       // classes per CTA tile
static constexpr int NTILES = (NCLS + TN - 1) / TN;     // 782

// ArcNegFace constants
static constexpr float COSM   = 0.87758256189037271612f;   // cos(0.5)
static constexpr float SINM   = 0.47942553860420300027f;   // sin(0.5)
static constexpr float THRESH = -0.87758256189037271612f;  // cos(pi-0.5)
static constexpr float MMC    = 0.23971276930210150014f;   // sin(pi-0.5)*0.5
static constexpr float EXP2C  = 0.72134752044448170368f;   // 1/(2*ln2)

// smem: 272B pitch rows (pad-8 bf16 -> conflict-free ldmatrix)
static constexpr int PITCH   = 272;
static constexpr int TILE_B  = 128 * PITCH;             // 34816
static constexpr int SM_BH  = 0;
static constexpr int SM_BL  = SM_BH + TILE_B;
static constexpr int SM_A0H = SM_BL + TILE_B;
static constexpr int SM_A0L = SM_A0H + TILE_B;
static constexpr int SM_A1H = SM_A0L + TILE_B;
static constexpr int SM_A1L = SM_A1H + TILE_B;
static constexpr int SMEM_BYTES = SM_A1L + TILE_B;      // 208896

// ---------------- device scratch (allocation-free rule) ----------------
__device__ unsigned long long g_Ahi[BATCH * DIM / 4];   // 4x bf16 packed
__device__ unsigned long long g_Alo[BATCH * DIM / 4];
__device__ float g_alb[BATCH];
__device__ int   g_lab[BATCH];

// ---------------- helpers ----------------
DEVI unsigned smem_u32(const void* p) {
    unsigned r;
    asm("{ .reg .u64 t; cvta.to.shared.u64 t, %1; cvt.u32.u64 %0, t; }"
        : "=r"(r) : "l"(p));
    return r;
}
DEVI float ex2f(float x) {
    float y;
    asm("ex2.approx.ftz.f32 %0, %1;" : "=f"(y) : "f"(x));
    return y;
}
DEVI void ldm_x4(unsigned& r0, unsigned& r1, unsigned& r2, unsigned& r3,
                 unsigned addr) {
    asm volatile("ldmatrix.sync.aligned.m8n8.x4.shared.b16 {%0,%1,%2,%3}, [%4];"
                 : "=r"(r0), "=r"(r1), "=r"(r2), "=r"(r3) : "r"(addr));
}
DEVI void mma16816(float* d, const unsigned* a, unsigned b0, unsigned b1) {
    asm volatile(
        "mma.sync.aligned.m16n8k16.row.col.f32.bf16.bf16.f32 "
        "{%0,%1,%2,%3}, {%4,%5,%6,%7}, {%8,%9}, {%0,%1,%2,%3};"
        : "+f"(d[0]), "+f"(d[1]), "+f"(d[2]), "+f"(d[3])
        : "r"(a[0]), "r"(a[1]), "r"(a[2]), "r"(a[3]), "r"(b0), "r"(b1));
}
DEVI void cpa16(unsigned dst, const void* src) {
    asm volatile("cp.async.cg.shared.global [%0], [%1], 16;"
                 :: "r"(dst), "l"(src) : "memory");
}
DEVI void cpa_commit() { asm volatile("cp.async.commit_group;" ::: "memory"); }
DEVI void cpa_wait_all() { asm volatile("cp.async.wait_group 0;" ::: "memory"); }
DEVI unsigned long long pack4(__nv_bfloat16 a, __nv_bfloat16 b,
                              __nv_bfloat16 c, __nv_bfloat16 d) {
    return (unsigned long long)__bfloat16_as_ushort(a)
         | ((unsigned long long)__bfloat16_as_ushort(b) << 16)
         | ((unsigned long long)__bfloat16_as_ushort(c) << 32)
         | ((unsigned long long)__bfloat16_as_ushort(d) << 48);
}
DEVI float rsqrt_ref(float s) {
    float r = rsqrtf(s);
    return r * (1.5f - 0.5f * s * r * r);   // Newton step -> ~fp32 exact
}
DEVI float anf(float cv, float a, float a64, bool isl) {
    float t  = cv - a;
    float rw = 1.2f * ex2f(-EXP2C * t * t);
    float v  = 64.0f * fmaf(rw, cv + 1.0f, -1.0f);
    return isl ? a64 : v;
}

// ============================================================================
// Prep: normalize feats -> split bf16 hi/lo globals; a_lb per row.
// ============================================================================
__global__ void prep_kernel(const float* __restrict__ feats,
                            const int* __restrict__ labels,
                            const float* __restrict__ weight) {
    int b = blockIdx.x * (blockDim.x >> 5) + (threadIdx.x >> 5);
    int lane = threadIdx.x & 31;
    if (b >= BATCH) return;

    float4 v = reinterpret_cast<const float4*>(feats)[b * 32 + lane];
    float s = v.x * v.x + v.y * v.y + v.z * v.z + v.w * v.w;
#pragma unroll
    for (int o = 16; o; o >>= 1) s += __shfl_xor_sync(0xffffffffu, s, o);
    float rinv = rsqrt_ref(s);
    float e0 = v.x * rinv, e1 = v.y * rinv, e2 = v.z * rinv, e3 = v.w * rinv;

    __nv_bfloat16 h0 = __float2bfloat16(e0), h1 = __float2bfloat16(e1);
    __nv_bfloat16 h2 = __float2bfloat16(e2), h3 = __float2bfloat16(e3);
    __nv_bfloat16 l0 = __float2bfloat16(e0 - __bfloat162float(h0));
    __nv_bfloat16 l1 = __float2bfloat16(e1 - __bfloat162float(h1));
    __nv_bfloat16 l2 = __float2bfloat16(e2 - __bfloat162float(h2));
    __nv_bfloat16 l3 = __float2bfloat16(e3 - __bfloat162float(h3));
    g_Ahi[b * 32 + lane] = pack4(h0, h1, h2, h3);
    g_Alo[b * 32 + lane] = pack4(l0, l1, l2, l3);

    int lab = labels[b];
    float4 wv = reinterpret_cast<const float4*>(weight)[(size_t)lab * 32 + lane];
    float sw = wv.x * wv.x + wv.y * wv.y + wv.z * wv.z + wv.w * wv.w;
    float dt = e0 * wv.x + e1 * wv.y + e2 * wv.z + e3 * wv.w;
#pragma unroll
    for (int o = 16; o; o >>= 1) sw += __shfl_xor_sync(0xffffffffu, sw, o);
#pragma unroll
    for (int o = 16; o; o >>= 1) dt += __shfl_xor_sync(0xffffffffu, dt, o);

    if (lane == 0) {
        float rw = rsqrt_ref(sw);
        float c = dt * rw;
        c = fminf(1.0f, fmaxf(-1.0f, c));
        float a = (c > THRESH)
                      ? (c * COSM - SINM * sqrtf(fmaxf(0.0f, 1.0f - c * c)))
                      : (c - MMC);
        g_alb[b] = a;
        g_lab[b] = lab;
    }
}

// ============================================================================
// Main: one CTA (512 thr, 16 warps) per 128-class tile.
// Warp grid 4(m) x 4(n): each warp m32 x n32. 4 M-tiles of 128 rows.
// A tiles double-buffered, filled by cp.async one M-tile ahead.
// ============================================================================
extern __shared__ char smem[];

__global__ void __launch_bounds__(512, 1)
arcneg_main(const float* __restrict__ weight, float* __restrict__ out) {
    unsigned sb = smem_u32(smem);
    int tid = threadIdx.x;
    int w = tid >> 5;          // 0..15
    int lane = tid & 31;
    int n0 = blockIdx.x * TN;
    int mw = w >> 2;           // 0..3 : m32 block
    int nw = w & 3;            // 0..3 : n32 block

    const unsigned bufH[2] = {SM_A0H, SM_A1H};
    const unsigned bufL[2] = {SM_A0L, SM_A1L};

    // issue cp.async fill for M-tile 0 into buffer 0 (overlaps B prologue)
    {
        const char* srcH = reinterpret_cast<const char*>(g_Ahi);
        const char* srcL = reinterpret_cast<const char*>(g_Alo);
#pragma unroll
        for (int j = tid; j < 2048; j += 512) {     // 16B chunks, 16 per row
            int row = j >> 4, cc = j & 15;
            unsigned off = row * PITCH + cc * 16;
            int gsrc = row * 256 + cc * 16;         // bytes into tile 0
            cpa16(sb + SM_A0H + off, srcH + gsrc);
            cpa16(sb + SM_A0L + off, srcL + gsrc);
        }
        cpa_commit();
    }

    // ---- Load + normalize + split weight tile (128 classes x 128 dims) ----
#pragma unroll 4
    for (int k = 0; k < 8; k++) {
        int r = k * 16 + w;
        int c = n0 + r;
        float4 v = make_float4(0.f, 0.f, 0.f, 0.f);
        if (c < NCLS) v = reinterpret_cast<const float4*>(weight)[(size_t)c * 32 + lane];
        float s = v.x * v.x + v.y * v.y + v.z * v.z + v.w * v.w;
#pragma unroll
        for (int o = 16; o; o >>= 1) s += __shfl_xor_sync(0xffffffffu, s, o);
        float rinv = 0.0f;
        if (c < NCLS && s > 1e-30f) rinv = rsqrt_ref(s);
        float e0 = v.x * rinv, e1 = v.y * rinv, e2 = v.z * rinv, e3 = v.w * rinv;
        __nv_bfloat16 h0 = __float2bfloat16(e0), h1 = __float2bfloat16(e1);
        __nv_bfloat16 h2 = __float2bfloat16(e2), h3 = __float2bfloat16(e3);
        __nv_bfloat16 l0 = __float2bfloat16(e0 - __bfloat162float(h0));
        __nv_bfloat16 l1 = __float2bfloat16(e1 - __bfloat162float(h1));
        __nv_bfloat16 l2 = __float2bfloat16(e2 - __bfloat162float(h2));
        __nv_bfloat16 l3 = __float2bfloat16(e3 - __bfloat162float(h3));
        unsigned off = r * PITCH + lane * 8;
        *reinterpret_cast<unsigned long long*>(smem + SM_BH + off) = pack4(h0, h1, h2, h3);
        *reinterpret_cast<unsigned long long*>(smem + SM_BL + off) = pack4(l0, l1, l2, l3);
    }

    // ldmatrix per-lane address patterns (within-tile byte offsets)
    const unsigned aL = (unsigned)((mw * 32 + (lane & 15)) * PITCH + ((lane & 16) >> 1) * 2);
    const unsigned bL = (unsigned)((nw * 32 + (lane & 7) + ((lane & 16) >> 1)) * PITCH + (lane & 8) * 2);

    int q = lane >> 2, rr = lane & 3;

#pragma unroll 1
    for (int mt = 0; mt < 4; mt++) {
        cpa_wait_all();        // buffer mt&1 data landed (this thread's copies)
        __syncthreads();       // all threads' copies visible; all warps done
                               // reading buffer (mt+1)&1 from iteration mt-1

        // prefetch next M-tile's A into the other buffer (overlaps mainloop)
        if (mt < 3) {
            const char* srcH = reinterpret_cast<const char*>(g_Ahi) + (mt + 1) * 32768;
            const char* srcL = reinterpret_cast<const char*>(g_Alo) + (mt + 1) * 32768;
            unsigned dH = sb + bufH[(mt + 1) & 1];
            unsigned dL = sb + bufL[(mt + 1) & 1];
#pragma unroll
            for (int j = tid; j < 2048; j += 512) {
                int row = j >> 4, cc = j & 15;
                unsigned off = row * PITCH + cc * 16;
                int gsrc = row * 256 + cc * 16;
                cpa16(dH + off, srcH + gsrc);
                cpa16(dL + off, srcL + gsrc);
            }
        }
        cpa_commit();          // commit (possibly empty) group every mt

        unsigned abH = sb + bufH[mt & 1] + aL;
        unsigned abL = sb + bufL[mt & 1] + aL;
        unsigned bbH = sb + SM_BH + bL;
        unsigned bbL = sb + SM_BL + bL;

        float acc[2][4][4];
#pragma unroll
        for (int i = 0; i < 2; i++)
#pragma unroll
            for (int j = 0; j < 4; j++)
#pragma unroll
                for (int e = 0; e < 4; e++) acc[i][j][e] = 0.0f;

        // ---- mainloop: per k-step load all 8 fragments once, 24 HMMA ----
#pragma unroll
        for (int k8 = 0; k8 < 8; k8++) {
            unsigned ka = k8 * 32;              // 16 bf16 = 32 bytes
            unsigned ah[2][4], al[2][4], bh[2][4], bl[2][4];
#pragma unroll
            for (int mi = 0; mi < 2; mi++)
                ldm_x4(ah[mi][0], ah[mi][1], ah[mi][2], ah[mi][3],
                       abH + mi * (16 * PITCH) + ka);
#pragma unroll
            for (int nj = 0; nj < 2; nj++)
                ldm_x4(bh[nj][0], bh[nj][1], bh[nj][2], bh[nj][3],
                       bbH + nj * (16 * PITCH) + ka);
#pragma unroll
            for (int mi = 0; mi < 2; mi++)
                ldm_x4(al[mi][0], al[mi][1], al[mi][2], al[mi][3],
                       abL + mi * (16 * PITCH) + ka);
#pragma unroll
            for (int nj = 0; nj < 2; nj++)
                ldm_x4(bl[nj][0], bl[nj][1], bl[nj][2], bl[nj][3],
                       bbL + nj * (16 * PITCH) + ka);

            // hi*hi
#pragma unroll
            for (int mi = 0; mi < 2; mi++)
#pragma unroll
                for (int ni = 0; ni < 4; ni++)
                    mma16816(acc[mi][ni], ah[mi],
                             bh[ni >> 1][(ni & 1) * 2],
                             bh[ni >> 1][(ni & 1) * 2 + 1]);
            // hi*lo
#pragma unroll
            for (int mi = 0; mi < 2; mi++)
#pragma unroll
                for (int ni = 0; ni < 4; ni++)
                    mma16816(acc[mi][ni], ah[mi],
                             bl[ni >> 1][(ni & 1) * 2],
                             bl[ni >> 1][(ni & 1) * 2 + 1]);
            // lo*hi
#pragma unroll
            for (int mi = 0; mi < 2; mi++)
#pragma unroll
                for (int ni = 0; ni < 4; ni++)
                    mma16816(acc[mi][ni], al[mi],
                             bh[ni >> 1][(ni & 1) * 2],
                             bh[ni >> 1][(ni & 1) * 2 + 1]);
        }

        // ---- fused epilogue, direct streaming v2 stores ----
#pragma unroll
        for (int mi = 0; mi < 2; mi++) {
            int r0 = mt * 128 + mw * 32 + mi * 16 + q;
            int r1 = r0 + 8;
            float av0 = g_alb[r0], av1 = g_alb[r1];
            int   lb0 = g_lab[r0], lb1 = g_lab[r1];
            float a64_0 = 64.0f * av0, a64_1 = 64.0f * av1;
#pragma unroll
            for (int ni = 0; ni < 4; ni++) {
                int c = n0 + nw * 32 + ni * 8 + rr * 2;
                if (c < NCLS) {
                    float2 v0, v1;
                    v0.x = anf(acc[mi][ni][0], av0, a64_0, c == lb0);
                    v0.y = anf(acc[mi][ni][1], av0, a64_0, c + 1 == lb0);
                    v1.x = anf(acc[mi][ni][2], av1, a64_1, c == lb1);
                    v1.y = anf(acc[mi][ni][3], av1, a64_1, c + 1 == lb1);
                    __stcs(reinterpret_cast<float2*>(out + (size_t)r0 * NCLS + c), v0);
                    __stcs(reinterpret_cast<float2*>(out + (size_t)r1 * NCLS + c), v1);
                }
            }
        }
    }
}

// ============================================================================
extern "C" void kernel_launch(void* const* d_in, const int* in_sizes, int n_in,
                              void* d_out, int out_size) {
    const float* feats = (const float*)d_in[0];
    const int*   labels = (const int*)d_in[1];
    const float* weight = (const float*)d_in[2];
    for (int i = 0; i < n_in; i++) {
        if (in_sizes[i] == BATCH * DIM) feats = (const float*)d_in[i];
        else if (in_sizes[i] == BATCH) labels = (const int*)d_in[i];
        else if (in_sizes[i] == NCLS * DIM) weight = (const float*)d_in[i];
    }
    float* out = (float*)d_out;

    cudaFuncSetAttribute(arcneg_main, cudaFuncAttributeMaxDynamicSharedMemorySize,
                         SMEM_BYTES);

    prep_kernel<<<128, 128>>>(feats, labels, weight);
    arcneg_main<<<NTILES, 512, SMEM_BYTES>>>(weight, out);
}

// round 11
// speedup vs baseline: 1.5521x; 1.0146x over previous
#include <cuda_runtime.h>
#include <cuda_bf16.h>

// ============================================================================
// ArcNegFace fused kernel for GB300 (compute_103 base target -> mma.sync path)
//   out[b,c] = 64 * ( onehot*a_lb + (1-onehot)*(rw*cos + rw - 1) )
//   cos = normalized feats @ normalized weight^T
//   Split-bf16 (hi+lo) 3-term MMA => fp32-grade cosine accuracy.
//   R11: TN=256 CTA tile, warp tile m64xn32 (HMMA:LDSM 3->4), staged term
//        loads for register fit; single A buffer with cp.async fill
//        overlapped with the epilogue.
// ============================================================================

#define DEVI __device__ __forceinline__

static constexpr int BATCH = 512;
static constexpr int DIM   = 128;
static constexpr int NCLS  = 100000;
static constexpr int TN    = 256;                       // classes per CTA tile
static constexpr int NTILES = (NCLS + TN - 1) / TN;     // 391

// ArcNegFace constants
static constexpr float COSM   = 0.87758256189037271612f;   // cos(0.5)
static constexpr float SINM   = 0.47942553860420300027f;   // sin(0.5)
static constexpr float THRESH = -0.87758256189037271612f;  // cos(pi-0.5)
static constexpr float MMC    = 0.23971276930210150014f;   // sin(pi-0.5)*0.5
static constexpr float EXP2C  = 0.72134752044448170368f;   // 1/(2*ln2)

// smem: 272B pitch rows (pad-8 bf16 -> conflict-free ldmatrix)
static constexpr int PITCH    = 272;
static constexpr int B_TILE_B = TN * PITCH;             // 69632
static constexpr int A_TILE_B = 128 * PITCH;            // 34816
static constexpr int SM_BH = 0;
static constexpr int SM_BL = SM_BH + B_TILE_B;
static constexpr int SM_AH = SM_BL + B_TILE_B;
static constexpr int SM_AL = SM_AH + A_TILE_B;
static constexpr int SMEM_BYTES = SM_AL + A_TILE_B;     // 208896

// ---------------- device scratch (allocation-free rule) ----------------
__device__ unsigned long long g_Ahi[BATCH * DIM / 4];   // 4x bf16 packed
__device__ unsigned long long g_Alo[BATCH * DIM / 4];
__device__ float g_alb[BATCH];
__device__ int   g_lab[BATCH];

// ---------------- helpers ----------------
DEVI unsigned smem_u32(const void* p) {
    unsigned r;
    asm("{ .reg .u64 t; cvta.to.shared.u64 t, %1; cvt.u32.u64 %0, t; }"
        : "=r"(r) : "l"(p));
    return r;
}
DEVI float ex2f(float x) {
    float y;
    asm("ex2.approx.ftz.f32 %0, %1;" : "=f"(y) : "f"(x));
    return y;
}
DEVI void ldm_x4(unsigned* r, unsigned addr) {
    asm volatile("ldmatrix.sync.aligned.m8n8.x4.shared.b16 {%0,%1,%2,%3}, [%4];"
                 : "=r"(r[0]), "=r"(r[1]), "=r"(r[2]), "=r"(r[3]) : "r"(addr));
}
DEVI void mma16816(float* d, const unsigned* a, unsigned b0, unsigned b1) {
    asm volatile(
        "mma.sync.aligned.m16n8k16.row.col.f32.bf16.bf16.f32 "
        "{%0,%1,%2,%3}, {%4,%5,%6,%7}, {%8,%9}, {%0,%1,%2,%3};"
        : "+f"(d[0]), "+f"(d[1]), "+f"(d[2]), "+f"(d[3])
        : "r"(a[0]), "r"(a[1]), "r"(a[2]), "r"(a[3]), "r"(b0), "r"(b1));
}
DEVI void cpa16(unsigned dst, const void* src) {
    asm volatile("cp.async.cg.shared.global [%0], [%1], 16;"
                 :: "r"(dst), "l"(src) : "memory");
}
DEVI void cpa_commit() { asm volatile("cp.async.commit_group;" ::: "memory"); }
DEVI void cpa_wait_all() { asm volatile("cp.async.wait_group 0;" ::: "memory"); }
DEVI unsigned long long pack4(__nv_bfloat16 a, __nv_bfloat16 b,
                              __nv_bfloat16 c, __nv_bfloat16 d) {
    return (unsigned long long)__bfloat16_as_ushort(a)
         | ((unsigned long long)__bfloat16_as_ushort(b) << 16)
         | ((unsigned long long)__bfloat16_as_ushort(c) << 32)
         | ((unsigned long long)__bfloat16_as_ushort(d) << 48);
}
DEVI float rsqrt_ref(float s) {
    float r = rsqrtf(s);
    return r * (1.5f - 0.5f * s * r * r);   // Newton step -> ~fp32 exact
}
DEVI float anf(float cv, float a, float a64, bool isl) {
    float t  = cv - a;
    float rw = 1.2f * ex2f(-EXP2C * t * t);
    float v  = 64.0f * fmaf(rw, cv + 1.0f, -1.0f);
    return isl ? a64 : v;
}

// ============================================================================
// Prep: normalize feats -> split bf16 hi/lo globals; a_lb per row.
// ============================================================================
__global__ void prep_kernel(const float* __restrict__ feats,
                            const int* __restrict__ labels,
                            const float* __restrict__ weight) {
    int b = blockIdx.x * (blockDim.x >> 5) + (threadIdx.x >> 5);
    int lane = threadIdx.x & 31;
    if (b >= BATCH) return;

    float4 v = reinterpret_cast<const float4*>(feats)[b * 32 + lane];
    float s = v.x * v.x + v.y * v.y + v.z * v.z + v.w * v.w;
#pragma unroll
    for (int o = 16; o; o >>= 1) s += __shfl_xor_sync(0xffffffffu, s, o);
    float rinv = rsqrt_ref(s);
    float e0 = v.x * rinv, e1 = v.y * rinv, e2 = v.z * rinv, e3 = v.w * rinv;

    __nv_bfloat16 h0 = __float2bfloat16(e0), h1 = __float2bfloat16(e1);
    __nv_bfloat16 h2 = __float2bfloat16(e2), h3 = __float2bfloat16(e3);
    __nv_bfloat16 l0 = __float2bfloat16(e0 - __bfloat162float(h0));
    __nv_bfloat16 l1 = __float2bfloat16(e1 - __bfloat162float(h1));
    __nv_bfloat16 l2 = __float2bfloat16(e2 - __bfloat162float(h2));
    __nv_bfloat16 l3 = __float2bfloat16(e3 - __bfloat162float(h3));
    g_Ahi[b * 32 + lane] = pack4(h0, h1, h2, h3);
    g_Alo[b * 32 + lane] = pack4(l0, l1, l2, l3);

    int lab = labels[b];
    float4 wv = reinterpret_cast<const float4*>(weight)[(size_t)lab * 32 + lane];
    float sw = wv.x * wv.x + wv.y * wv.y + wv.z * wv.z + wv.w * wv.w;
    float dt = e0 * wv.x + e1 * wv.y + e2 * wv.z + e3 * wv.w;
#pragma unroll
    for (int o = 16; o; o >>= 1) sw += __shfl_xor_sync(0xffffffffu, sw, o);
#pragma unroll
    for (int o = 16; o; o >>= 1) dt += __shfl_xor_sync(0xffffffffu, dt, o);

    if (lane == 0) {
        float rw = rsqrt_ref(sw);
        float c = dt * rw;
        c = fminf(1.0f, fmaxf(-1.0f, c));
        float a = (c > THRESH)
                      ? (c * COSM - SINM * sqrtf(fmaxf(0.0f, 1.0f - c * c)))
                      : (c - MMC);
        g_alb[b] = a;
        g_lab[b] = lab;
    }
}

// ============================================================================
// Main: one CTA (512 thr, 16 warps) per 256-class tile.
// Warp grid 2(m) x 8(n): each warp m64 x n32. 4 M-tiles of 128 rows.
// Single A buffer, cp.async-filled one M-tile ahead (overlaps epilogue).
// ============================================================================
extern __shared__ char smem[];

__global__ void __launch_bounds__(512, 1)
arcneg_main(const float* __restrict__ weight, float* __restrict__ out) {
    unsigned sb = smem_u32(smem);
    int tid = threadIdx.x;
    int w = tid >> 5;          // 0..15
    int lane = tid & 31;
    int n0 = blockIdx.x * TN;
    int mw = w >> 3;           // 0..1 : m64 block
    int nw = w & 7;            // 0..7 : n32 block

    // issue cp.async fill for M-tile 0 (overlaps B prologue)
    {
        const char* srcH = reinterpret_cast<const char*>(g_Ahi);
        const char* srcL = reinterpret_cast<const char*>(g_Alo);
#pragma unroll
        for (int j = tid; j < 2048; j += 512) {     // 16B chunks, 16 per row
            int row = j >> 4, cc = j & 15;
            unsigned off = row * PITCH + cc * 16;
            int gsrc = row * 256 + cc * 16;
            cpa16(sb + SM_AH + off, srcH + gsrc);
            cpa16(sb + SM_AL + off, srcL + gsrc);
        }
        cpa_commit();
    }

    // ---- Load + normalize + split weight tile (256 classes x 128 dims) ----
#pragma unroll 4
    for (int k = 0; k < 16; k++) {
        int r = k * 16 + w;
        int c = n0 + r;
        float4 v = make_float4(0.f, 0.f, 0.f, 0.f);
        if (c < NCLS) v = reinterpret_cast<const float4*>(weight)[(size_t)c * 32 + lane];
        float s = v.x * v.x + v.y * v.y + v.z * v.z + v.w * v.w;
#pragma unroll
        for (int o = 16; o; o >>= 1) s += __shfl_xor_sync(0xffffffffu, s, o);
        float rinv = 0.0f;
        if (c < NCLS && s > 1e-30f) rinv = rsqrt_ref(s);
        float e0 = v.x * rinv, e1 = v.y * rinv, e2 = v.z * rinv, e3 = v.w * rinv;
        __nv_bfloat16 h0 = __float2bfloat16(e0), h1 = __float2bfloat16(e1);
        __nv_bfloat16 h2 = __float2bfloat16(e2), h3 = __float2bfloat16(e3);
        __nv_bfloat16 l0 = __float2bfloat16(e0 - __bfloat162float(h0));
        __nv_bfloat16 l1 = __float2bfloat16(e1 - __bfloat162float(h1));
        __nv_bfloat16 l2 = __float2bfloat16(e2 - __bfloat162float(h2));
        __nv_bfloat16 l3 = __float2bfloat16(e3 - __bfloat162float(h3));
        unsigned off = r * PITCH + lane * 8;
        *reinterpret_cast<unsigned long long*>(smem + SM_BH + off) = pack4(h0, h1, h2, h3);
        *reinterpret_cast<unsigned long long*>(smem + SM_BL + off) = pack4(l0, l1, l2, l3);
    }
    cpa_wait_all();
    __syncthreads();           // B visible + A(0) landed

    // ldmatrix per-lane address patterns (within-tile byte offsets)
    const unsigned aL = (unsigned)((mw * 64 + (lane & 15)) * PITCH + ((lane & 16) >> 1) * 2);
    const unsigned bL = (unsigned)((nw * 32 + (lane & 7) + ((lane & 16) >> 1)) * PITCH + (lane & 8) * 2);

    const unsigned abH = sb + SM_AH + aL;
    const unsigned abL = sb + SM_AL + aL;
    const unsigned bbH = sb + SM_BH + bL;
    const unsigned bbL = sb + SM_BL + bL;

    int q = lane >> 2, rr = lane & 3;

#pragma unroll 1
    for (int mt = 0; mt < 4; mt++) {
        float acc[4][4][4];
#pragma unroll
        for (int i = 0; i < 4; i++)
#pragma unroll
            for (int j = 0; j < 4; j++)
#pragma unroll
                for (int e = 0; e < 4; e++) acc[i][j][e] = 0.0f;

        // ---- mainloop: per k-step 12 LDSM / 48 HMMA, staged term loads ----
#pragma unroll
        for (int k8 = 0; k8 < 8; k8++) {
            unsigned ka = k8 * 32;              // 16 bf16 = 32 bytes
            unsigned ah[4][4], bh[2][4];
#pragma unroll
            for (int mi = 0; mi < 4; mi++)
                ldm_x4(ah[mi], abH + mi * (16 * PITCH) + ka);
#pragma unroll
            for (int nj = 0; nj < 2; nj++)
                ldm_x4(bh[nj], bbH + nj * (16 * PITCH) + ka);

            // hi*hi
#pragma unroll
            for (int mi = 0; mi < 4; mi++)
#pragma unroll
                for (int ni = 0; ni < 4; ni++)
                    mma16816(acc[mi][ni], ah[mi],
                             bh[ni >> 1][(ni & 1) * 2],
                             bh[ni >> 1][(ni & 1) * 2 + 1]);

            {   // hi*lo (B-lo fragments live only here)
                unsigned bl[2][4];
#pragma unroll
                for (int nj = 0; nj < 2; nj++)
                    ldm_x4(bl[nj], bbL + nj * (16 * PITCH) + ka);
#pragma unroll
                for (int mi = 0; mi < 4; mi++)
#pragma unroll
                    for (int ni = 0; ni < 4; ni++)
                        mma16816(acc[mi][ni], ah[mi],
                                 bl[ni >> 1][(ni & 1) * 2],
                                 bl[ni >> 1][(ni & 1) * 2 + 1]);
            }
            {   // lo*hi (A-lo fragments can reuse A-hi registers)
                unsigned al[4][4];
#pragma unroll
                for (int mi = 0; mi < 4; mi++)
                    ldm_x4(al[mi], abL + mi * (16 * PITCH) + ka);
#pragma unroll
                for (int mi = 0; mi < 4; mi++)
#pragma unroll
                    for (int ni = 0; ni < 4; ni++)
                        mma16816(acc[mi][ni], al[mi],
                                 bh[ni >> 1][(ni & 1) * 2],
                                 bh[ni >> 1][(ni & 1) * 2 + 1]);
            }
        }
        __syncthreads();       // all warps done reading A(mt)

        // prefetch next M-tile's A (overlaps epilogue below)
        if (mt < 3) {
            const char* srcH = reinterpret_cast<const char*>(g_Ahi) + (mt + 1) * 32768;
            const char* srcL = reinterpret_cast<const char*>(g_Alo) + (mt + 1) * 32768;
#pragma unroll
            for (int j = tid; j < 2048; j += 512) {
                int row = j >> 4, cc = j & 15;
                unsigned off = row * PITCH + cc * 16;
                int gsrc = row * 256 + cc * 16;
                cpa16(sb + SM_AH + off, srcH + gsrc);
                cpa16(sb + SM_AL + off, srcL + gsrc);
            }
        }
        cpa_commit();

        // ---- fused epilogue, direct streaming v2 stores ----
#pragma unroll
        for (int mi = 0; mi < 4; mi++) {
            int r0 = mt * 128 + mw * 64 + mi * 16 + q;
            int r1 = r0 + 8;
            float av0 = g_alb[r0], av1 = g_alb[r1];
            int   lb0 = g_lab[r0], lb1 = g_lab[r1];
            float a64_0 = 64.0f * av0, a64_1 = 64.0f * av1;
#pragma unroll
            for (int ni = 0; ni < 4; ni++) {
                int c = n0 + nw * 32 + ni * 8 + rr * 2;
                if (c < NCLS) {
                    float2 v0, v1;
                    v0.x = anf(acc[mi][ni][0], av0, a64_0, c == lb0);
                    v0.y = anf(acc[mi][ni][1], av0, a64_0, c + 1 == lb0);
                    v1.x = anf(acc[mi][ni][2], av1, a64_1, c == lb1);
                    v1.y = anf(acc[mi][ni][3], av1, a64_1, c + 1 == lb1);
                    __stcs(reinterpret_cast<float2*>(out + (size_t)r0 * NCLS + c), v0);
                    __stcs(reinterpret_cast<float2*>(out + (size_t)r1 * NCLS + c), v1);
                }
            }
        }

        if (mt < 3) {
            cpa_wait_all();    // A(mt+1) landed (fills overlapped the epilogue)
            __syncthreads();
        }
    }
}

// ============================================================================
extern "C" void kernel_launch(void* const* d_in, const int* in_sizes, int n_in,
                              void* d_out, int out_size) {
    const float* feats = (const float*)d_in[0];
    const int*   labels = (const int*)d_in[1];
    const float* weight = (const float*)d_in[2];
    for (int i = 0; i < n_in; i++) {
        if (in_sizes[i] == BATCH * DIM) feats = (const float*)d_in[i];
        else if (in_sizes[i] == BATCH) labels = (const int*)d_in[i];
        else if (in_sizes[i] == NCLS * DIM) weight = (const float*)d_in[i];
    }
    float* out = (float*)d_out;

    cudaFuncSetAttribute(arcneg_main, cudaFuncAttributeMaxDynamicSharedMemorySize,
                         SMEM_BYTES);

    prep_kernel<<<128, 128>>>(feats, labels, weight);
    arcneg_main<<<NTILES, 512, SMEM_BYTES>>>(weight, out);
}